// round 17
// baseline (speedup 1.0000x reference)
#include <cuda_runtime.h>
#include <math.h>

#define DD 64
#define TWO_PI_F 6.283185307179586f
#define EPS_F 1e-8f

// Device-side state (no allocations allowed; all zero-initialized at load).
__device__ __align__(16) float g_diag[DD];
__device__ float g_invA[DD * DD];
__device__ float g_coef;
__device__ int g_isdiag;
__device__ int g_ready;                 // leader sets 1; last block resets 0
__device__ unsigned int g_done;         // completion counter for reset
__device__ float g_aug[DD][2 * DD];     // cold-path GJ scratch (global, leader-only)

// ---------------------------------------------------------------------------
// Single fused kernel. Block 0 = leader: runs prep (diag check + coef, or
// full Gauss-Jordan on non-diagonal Sigma), publishes g_*, sets g_ready.
// All other blocks front-batch their 4 sample LDG.128s + mu FIRST (overlaps
// the leader's prep), then one thread polls g_ready (volatile + nanosleep),
// barrier-broadcasts, and the proven hot body runs: 4 samples/thread,
// half-warp per 4-sample group, 4 shfl trees, one STG.128.
// Self-resetting: last block to finish clears g_ready/g_done so every graph
// replay starts from the same state (deterministic, no caching).
// ---------------------------------------------------------------------------
__global__ void __launch_bounds__(256, 8)
fused_kernel(const float* __restrict__ x,
             const float* __restrict__ Phi,
             const float* __restrict__ mu,
             const float* __restrict__ Sigma,
             float* __restrict__ out, int N) {
    __shared__ float sdiag[DD];
    __shared__ float colk[DD];
    __shared__ float s_wprod[2];
    __shared__ int s_offdiag;
    __shared__ float s_det;
    __shared__ int s_piv;

    int tid = threadIdx.x;
    int lane = tid & 31;
    int wid = tid >> 5;
    int half = lane >> 4;          // 0 or 1
    int sub = lane & 15;           // 16B chunk within sample
    int warp_g = (blockIdx.x * blockDim.x + tid) >> 5;
    int base = warp_g * 8 + half * 4;   // first of this thread's 4 samples
    bool have = (base < N);
    bool leader_blk = (blockIdx.x == 0);

    const float4* xr = reinterpret_cast<const float4*>(x);
    float4 xv0, xv1, xv2, xv3, muv;

    if (!leader_blk) {
        // ---- Prologue overlaps leader's prep: front-batched MLP=4 ----
        if (have) {
            xv0 = xr[(size_t)(base + 0) * 16 + sub];
            xv1 = xr[(size_t)(base + 1) * 16 + sub];
            xv2 = xr[(size_t)(base + 2) * 16 + sub];
            xv3 = xr[(size_t)(base + 3) * 16 + sub];
            muv = reinterpret_cast<const float4*>(mu)[sub];
        }
        // One poll thread per block; others park at the barrier.
        if (tid == 0) {
            while (*(volatile int*)&g_ready == 0) __nanosleep(32);
            __threadfence();   // acquire: order subsequent g_* loads
        }
        __syncthreads();
    } else {
        // ================= Leader block: prep =================
        if (tid == 0) s_offdiag = 0;
        __syncthreads();

        // Vectorized Sigma pass: 1024 float4, 256 threads x 4 each.
        {
            const float4* S4 = reinterpret_cast<const float4*>(Sigma);
            int bad = 0;
            #pragma unroll
            for (int q = 0; q < 4; q++) {
                float4 c = S4[tid * 4 + q];
                int ebase = (tid * 4 + q) * 4;
                float vals[4] = {c.x, c.y, c.z, c.w};
                #pragma unroll
                for (int i = 0; i < 4; i++) {
                    int e = ebase + i;
                    int r = e >> 6, col = e & 63;
                    if (r == col) sdiag[r] = vals[i];
                    else if (vals[i] != 0.0f) bad = 1;
                }
            }
            if (bad) atomicOr(&s_offdiag, 1);
        }
        __syncthreads();

        if (!s_offdiag) {
            // Diagonal fast prep: reciprocals + shfl-product det.
            if (tid < DD) {
                float v = sdiag[tid];
                g_diag[tid] = (v != 0.0f) ? 1.0f / v : 0.0f;  // pinv semantics
                float p = v;
                #pragma unroll
                for (int m = 16; m >= 1; m >>= 1)
                    p *= __shfl_xor_sync(0xffffffffu, p, m);
                if (lane == 0) s_wprod[wid] = p;
            }
            __syncthreads();
            if (tid == 0) {
                float det = s_wprod[0] * s_wprod[1];
                g_coef = Phi[0] / sqrtf(TWO_PI_F * det);
                g_isdiag = 1;
            }
        } else {
            // General path: Gauss-Jordan w/ partial pivoting in global scratch.
            for (int i = tid; i < DD * 2 * DD; i += blockDim.x) {
                int r = i / (2 * DD), c = i % (2 * DD);
                g_aug[r][c] = (c < DD) ? Sigma[r * DD + c]
                                       : ((c - DD == r) ? 1.0f : 0.0f);
            }
            if (tid == 0) s_det = 1.0f;
            __syncthreads();

            for (int k = 0; k < DD; k++) {
                if (tid == 0) {
                    int p = k;
                    float best = fabsf(g_aug[k][k]);
                    for (int r = k + 1; r < DD; r++) {
                        float v = fabsf(g_aug[r][k]);
                        if (v > best) { best = v; p = r; }
                    }
                    s_piv = p;
                    if (p != k) s_det = -s_det;
                }
                __syncthreads();
                int p = s_piv;
                if (p != k) {
                    for (int c = tid; c < 2 * DD; c += blockDim.x) {
                        float t = g_aug[k][c];
                        g_aug[k][c] = g_aug[p][c];
                        g_aug[p][c] = t;
                    }
                    __syncthreads();
                }
                float piv = g_aug[k][k];
                if (tid == 0) s_det *= piv;
                float inv_piv = (piv != 0.0f) ? 1.0f / piv : 0.0f;
                for (int c = tid; c < 2 * DD; c += blockDim.x)
                    g_aug[k][c] *= inv_piv;
                if (tid < DD) colk[tid] = (tid == k) ? 0.0f : g_aug[tid][k];
                __syncthreads();
                for (int i = tid; i < DD * 2 * DD; i += blockDim.x) {
                    int r = i / (2 * DD), c = i % (2 * DD);
                    if (r != k) g_aug[r][c] -= colk[r] * g_aug[k][c];
                }
                __syncthreads();
            }

            for (int i = tid; i < DD * DD; i += blockDim.x) {
                int r = i >> 6, c = i & 63;
                g_invA[i] = g_aug[r][DD + c];
            }
            if (tid == 0) {
                g_coef = Phi[0] / sqrtf(TWO_PI_F * s_det);
                g_isdiag = 0;
            }
        }
        __syncthreads();
        if (tid == 0) {
            __threadfence();                    // publish g_* (release)
            *(volatile int*)&g_ready = 1;
        }

        // Leader's own sample loads (after prep; tiny fraction of the grid).
        if (have) {
            xv0 = xr[(size_t)(base + 0) * 16 + sub];
            xv1 = xr[(size_t)(base + 1) * 16 + sub];
            xv2 = xr[(size_t)(base + 2) * 16 + sub];
            xv3 = xr[(size_t)(base + 3) * 16 + sub];
            muv = reinterpret_cast<const float4*>(mu)[sub];
        }
    }

    // ================= Density body (all blocks) =================
    if (have) {
        if (g_isdiag) {
            float4 av = reinterpret_cast<const float4*>(g_diag)[sub];

            float p0, p1, p2, p3;
            {
                float d0 = xv0.x - muv.x, d1 = xv0.y - muv.y,
                      d2 = xv0.z - muv.z, d3 = xv0.w - muv.w;
                p0 = av.x * d0 * d0 + av.y * d1 * d1 + av.z * d2 * d2 + av.w * d3 * d3;
            }
            {
                float d0 = xv1.x - muv.x, d1 = xv1.y - muv.y,
                      d2 = xv1.z - muv.z, d3 = xv1.w - muv.w;
                p1 = av.x * d0 * d0 + av.y * d1 * d1 + av.z * d2 * d2 + av.w * d3 * d3;
            }
            {
                float d0 = xv2.x - muv.x, d1 = xv2.y - muv.y,
                      d2 = xv2.z - muv.z, d3 = xv2.w - muv.w;
                p2 = av.x * d0 * d0 + av.y * d1 * d1 + av.z * d2 * d2 + av.w * d3 * d3;
            }
            {
                float d0 = xv3.x - muv.x, d1 = xv3.y - muv.y,
                      d2 = xv3.z - muv.z, d3 = xv3.w - muv.w;
                p3 = av.x * d0 * d0 + av.y * d1 * d1 + av.z * d2 * d2 + av.w * d3 * d3;
            }

            #pragma unroll
            for (int m = 8; m >= 1; m >>= 1) {
                p0 += __shfl_xor_sync(0xffffffffu, p0, m);
                p1 += __shfl_xor_sync(0xffffffffu, p1, m);
                p2 += __shfl_xor_sync(0xffffffffu, p2, m);
                p3 += __shfl_xor_sync(0xffffffffu, p3, m);
            }

            if (sub == 0) {
                float coef = g_coef;
                float4 r;
                r.x = -__logf(coef * __expf(-0.5f * p0) + EPS_F);
                r.y = -__logf(coef * __expf(-0.5f * p1) + EPS_F);
                r.z = -__logf(coef * __expf(-0.5f * p2) + EPS_F);
                r.w = -__logf(coef * __expf(-0.5f * p3) + EPS_F);
                *reinterpret_cast<float4*>(out + base) = r;
            }
        } else {
            // General quadratic form (cold path).
            if (sub == 0) {
                for (int j = 0; j < 4; j++) {
                    int s = base + j;
                    if (s >= N) break;
                    const float* xrow = x + (size_t)s * DD;
                    float q = 0.0f;
#pragma unroll 1
                    for (int e = 0; e < DD; e++) {
                        float de = xrow[e] - mu[e];
                        float t = 0.0f;
#pragma unroll 8
                        for (int d = 0; d < DD; d++)
                            t += g_invA[e * DD + d] * (xrow[d] - mu[d]);
                        q += de * t;
                    }
                    float dens = g_coef * __expf(-0.5f * q);
                    out[s] = -__logf(dens + EPS_F);
                }
            }
        }
    }

    // ---- Self-reset for the next graph replay (deterministic) ----
    __syncthreads();
    if (tid == 0) {
        unsigned int t = atomicAdd(&g_done, 1u);
        if (t == gridDim.x - 1u) {          // last block: everyone passed the wait
            g_done = 0u;
            __threadfence();
            *(volatile int*)&g_ready = 0;
        }
    }
}

extern "C" void kernel_launch(void* const* d_in, const int* in_sizes, int n_in,
                              void* d_out, int out_size) {
    const float* samples = (const float*)d_in[0];
    const float* Phi     = (const float*)d_in[1];
    const float* mu      = (const float*)d_in[2];
    const float* Sigma   = (const float*)d_in[3];
    int N = out_size;  // one output per sample

    long long total = (long long)N * 4;   // 4 samples/thread, 16 lanes/sample
    int threads = 256;
    int blocks = (int)((total + threads - 1) / threads);

    fused_kernel<<<blocks, threads>>>(samples, Phi, mu, Sigma,
                                      (float*)d_out, N);
}